// round 15
// baseline (speedup 1.0000x reference)
#include <cuda_runtime.h>
#include <cuda_bf16.h>

// MRPCEN: multi-rate PCEN.
//   x: (32,128,2000) f32 ; log_alpha/log_delta/log_r: (128,) f32
//   out: (32,4,128,2000) f32, out[b,t,f,k]
// Per time-constant t: s = (sqrt(1+4t^2)-1)/(2t^2); IIR m[k]=(1-s)m[k-1]+s x[k], m[0]=x[0].
// smooth = (eps+M)^(-alpha); pcen = (x*smooth+delta)^r - delta^r.
//
// One block per (b,f) row. 512 threads = 4 groups x 128 threads (group = one t).
// x row staged in padded smem. Constant-coefficient parallel scan:
//   chunk length 16, carry factor A16=(1-s)^16, Kogge-Stone warp scan with
//   factor squaring, 3-step cross-warp combine. Exact algebra, all-positive
//   terms -> no cancellation.

#define TLEN 2000

__device__ __forceinline__ float ex2f_fast(float x) {
    float y; asm("ex2.approx.f32 %0, %1;" : "=f"(y) : "f"(x)); return y;
}
__device__ __forceinline__ float lg2f_fast(float x) {
    float y; asm("lg2.approx.f32 %0, %1;" : "=f"(y) : "f"(x)); return y;
}

__global__ void __launch_bounds__(512, 2)
mrpcen_kernel(const float* __restrict__ x,
              const float* __restrict__ log_alpha,
              const float* __restrict__ log_delta,
              const float* __restrict__ log_r,
              float* __restrict__ out)
{
    __shared__ float xs[2048 + 128];   // padded: index i stored at i + (i>>4)
    __shared__ float wsum[16];         // 4 groups x 4 warps

    const int bf = blockIdx.x;         // b*128 + f
    const int f  = bf & 127;
    const float* __restrict__ xrow = x + (long)bf * TLEN;

    const int tid = threadIdx.x;

    // ---- stage x row into smem (coalesced) ----
    #pragma unroll
    for (int i = 0; i < 4; ++i) {
        int idx = tid + i * 512;
        if (idx < TLEN) xs[idx + (idx >> 4)] = xrow[idx];
    }
    __syncthreads();

    const int g = tid >> 7;            // which time constant
    const int r = tid & 127;           // chunk index within row
    const int l = r & 31;              // lane in warp
    const int w = r >> 5;              // warp within group

    const float tconst = (g == 0) ? 4.f : (g == 1) ? 16.f : (g == 2) ? 64.f : 256.f;
    const float s = (sqrtf(fmaf(4.f * tconst, tconst, 1.f)) - 1.f) / (2.f * tconst * tconst);
    const float A = 1.f - s;
    const float A2 = A * A, A4 = A2 * A2, A8 = A4 * A4;
    const float A16 = A8 * A8;                                   // exact-ish via squaring
    const float log2A16 = 16.f * (log1pf(-s) * 1.4426950408889634f);

    const float x0 = xs[0];
    const int base = r * 16;           // first T index of this chunk
    const int sb   = 17 * r;           // padded smem base of this chunk

    // ---- pass 1: local chunk partial q (zero initial state) ----
    float q = 0.f;
    if (base < TLEN) {
        #pragma unroll
        for (int k = 0; k < 16; ++k)
            q = fmaf(A, q, s * xs[sb + k]);
    }

    // ---- warp-level Kogge-Stone scan of q with factor A16 ----
    float S  = q;
    float pw = A16;
    #pragma unroll
    for (int d = 1; d < 32; d <<= 1) {
        float up = __shfl_up_sync(0xffffffffu, S, d);
        if (l >= d) S = fmaf(pw, up, S);
        pw *= pw;                      // A16^(2d)
    }
    const float A16_32 = pw;           // A16^32

    if (l == 31) wsum[(g << 2) + w] = S;
    __syncthreads();

    // cross-warp incoming state H_w = scan value entering this warp
    float H = 0.f;
    #pragma unroll
    for (int v = 0; v < 3; ++v)
        if (v < w) H = fmaf(A16_32, H, wsum[(g << 2) + v]);

    // exclusive scan value for this chunk: E = A16^l * H + S_{l-1}
    float Sprev = __shfl_up_sync(0xffffffffu, S, 1);
    if (l == 0) Sprev = 0.f;
    const float E = fmaf(ex2f_fast(log2A16 * (float)l), H, Sprev);

    // state entering this chunk: m_start = A16^r * x0 + E   (m[-1] = x0)
    float m = fmaf(ex2f_fast(log2A16 * (float)r), x0, E);

    // ---- per-feature parameters ----
    const float alpha   = __expf(log_alpha[f]);
    const float delta   = __expf(log_delta[f]);
    const float rr      = __expf(log_r[f]);
    const float delta_r = ex2f_fast(rr * lg2f_fast(delta));
    const float nalpha  = -alpha;

    // ---- pass 2: recompute m with true state, PCEN math, float4 stores ----
    if (base < TLEN) {
        float* __restrict__ orow =
            out + ((((long)(bf >> 7)) * 4 + g) * 128 + f) * (long)TLEN + base;
        #pragma unroll
        for (int k4 = 0; k4 < 4; ++k4) {
            float4 v;
            float* vp = reinterpret_cast<float*>(&v);
            #pragma unroll
            for (int k = 0; k < 4; ++k) {
                const float xv = xs[sb + k4 * 4 + k];
                m = fmaf(A, m, s * xv);
                const float smooth = ex2f_fast(nalpha * lg2f_fast(m + 1e-5f));
                vp[k] = ex2f_fast(rr * lg2f_fast(fmaf(xv, smooth, delta))) - delta_r;
            }
            reinterpret_cast<float4*>(orow)[k4] = v;
        }
    }
}

extern "C" void kernel_launch(void* const* d_in, const int* in_sizes, int n_in,
                              void* d_out, int out_size)
{
    const float* x  = (const float*)d_in[0];
    const float* la = (const float*)d_in[1];
    const float* ld = (const float*)d_in[2];
    const float* lr = (const float*)d_in[3];
    float* out = (float*)d_out;

    // grid = B*F = 32*128 = 4096 blocks, 512 threads (4 t-groups x 128 chunks)
    mrpcen_kernel<<<4096, 512>>>(x, la, ld, lr, out);
}

// round 16
// speedup vs baseline: 1.0005x; 1.0005x over previous
#include <cuda_runtime.h>
#include <cuda_bf16.h>

// MRPCEN: multi-rate PCEN.
//   x: (32,128,2000) f32 ; log_alpha/log_delta/log_r: (128,) f32
//   out: (32,4,128,2000) f32, out[b,t,f,k]
// Per time-constant t: s = (sqrt(1+4t^2)-1)/(2t^2); IIR m[k]=(1-s)m[k-1]+s x[k], m[0]=x[0].
// smooth = (eps+M)^(-alpha); pcen = (x*smooth+delta)^r - delta^r.
//
// One block per (b,f) row. 512 threads = 4 groups x 128 threads (group = one t).
// x row staged in padded smem. Constant-coefficient parallel scan:
//   chunk length 16, carry factor A16=(1-s)^16, Kogge-Stone warp scan with
//   factor squaring, 3-step cross-warp combine. Exact algebra, all-positive
//   terms -> no cancellation.

#define TLEN 2000

__device__ __forceinline__ float ex2f_fast(float x) {
    float y; asm("ex2.approx.f32 %0, %1;" : "=f"(y) : "f"(x)); return y;
}
__device__ __forceinline__ float lg2f_fast(float x) {
    float y; asm("lg2.approx.f32 %0, %1;" : "=f"(y) : "f"(x)); return y;
}

__global__ void __launch_bounds__(512, 2)
mrpcen_kernel(const float* __restrict__ x,
              const float* __restrict__ log_alpha,
              const float* __restrict__ log_delta,
              const float* __restrict__ log_r,
              float* __restrict__ out)
{
    __shared__ float xs[2048 + 128];   // padded: index i stored at i + (i>>4)
    __shared__ float wsum[16];         // 4 groups x 4 warps

    const int bf = blockIdx.x;         // b*128 + f
    const int f  = bf & 127;
    const float* __restrict__ xrow = x + (long)bf * TLEN;

    const int tid = threadIdx.x;

    // ---- stage x row into smem (coalesced) ----
    #pragma unroll
    for (int i = 0; i < 4; ++i) {
        int idx = tid + i * 512;
        if (idx < TLEN) xs[idx + (idx >> 4)] = xrow[idx];
    }
    __syncthreads();

    const int g = tid >> 7;            // which time constant
    const int r = tid & 127;           // chunk index within row
    const int l = r & 31;              // lane in warp
    const int w = r >> 5;              // warp within group

    const float tconst = (g == 0) ? 4.f : (g == 1) ? 16.f : (g == 2) ? 64.f : 256.f;
    const float s = (sqrtf(fmaf(4.f * tconst, tconst, 1.f)) - 1.f) / (2.f * tconst * tconst);
    const float A = 1.f - s;
    const float A2 = A * A, A4 = A2 * A2, A8 = A4 * A4;
    const float A16 = A8 * A8;                                   // exact-ish via squaring
    const float log2A16 = 16.f * (log1pf(-s) * 1.4426950408889634f);

    const float x0 = xs[0];
    const int base = r * 16;           // first T index of this chunk
    const int sb   = 17 * r;           // padded smem base of this chunk

    // ---- pass 1: local chunk partial q (zero initial state) ----
    float q = 0.f;
    if (base < TLEN) {
        #pragma unroll
        for (int k = 0; k < 16; ++k)
            q = fmaf(A, q, s * xs[sb + k]);
    }

    // ---- warp-level Kogge-Stone scan of q with factor A16 ----
    float S  = q;
    float pw = A16;
    #pragma unroll
    for (int d = 1; d < 32; d <<= 1) {
        float up = __shfl_up_sync(0xffffffffu, S, d);
        if (l >= d) S = fmaf(pw, up, S);
        pw *= pw;                      // A16^(2d)
    }
    const float A16_32 = pw;           // A16^32

    if (l == 31) wsum[(g << 2) + w] = S;
    __syncthreads();

    // cross-warp incoming state H_w = scan value entering this warp
    float H = 0.f;
    #pragma unroll
    for (int v = 0; v < 3; ++v)
        if (v < w) H = fmaf(A16_32, H, wsum[(g << 2) + v]);

    // exclusive scan value for this chunk: E = A16^l * H + S_{l-1}
    float Sprev = __shfl_up_sync(0xffffffffu, S, 1);
    if (l == 0) Sprev = 0.f;
    const float E = fmaf(ex2f_fast(log2A16 * (float)l), H, Sprev);

    // state entering this chunk: m_start = A16^r * x0 + E   (m[-1] = x0)
    float m = fmaf(ex2f_fast(log2A16 * (float)r), x0, E);

    // ---- per-feature parameters ----
    const float alpha   = __expf(log_alpha[f]);
    const float delta   = __expf(log_delta[f]);
    const float rr      = __expf(log_r[f]);
    const float delta_r = ex2f_fast(rr * lg2f_fast(delta));
    const float nalpha  = -alpha;

    // ---- pass 2: recompute m with true state, PCEN math, float4 stores ----
    if (base < TLEN) {
        float* __restrict__ orow =
            out + ((((long)(bf >> 7)) * 4 + g) * 128 + f) * (long)TLEN + base;
        #pragma unroll
        for (int k4 = 0; k4 < 4; ++k4) {
            float4 v;
            float* vp = reinterpret_cast<float*>(&v);
            #pragma unroll
            for (int k = 0; k < 4; ++k) {
                const float xv = xs[sb + k4 * 4 + k];
                m = fmaf(A, m, s * xv);
                const float smooth = ex2f_fast(nalpha * lg2f_fast(m + 1e-5f));
                vp[k] = ex2f_fast(rr * lg2f_fast(fmaf(xv, smooth, delta))) - delta_r;
            }
            reinterpret_cast<float4*>(orow)[k4] = v;
        }
    }
}

extern "C" void kernel_launch(void* const* d_in, const int* in_sizes, int n_in,
                              void* d_out, int out_size)
{
    const float* x  = (const float*)d_in[0];
    const float* la = (const float*)d_in[1];
    const float* ld = (const float*)d_in[2];
    const float* lr = (const float*)d_in[3];
    float* out = (float*)d_out;

    // grid = B*F = 32*128 = 4096 blocks, 512 threads (4 t-groups x 128 chunks)
    mrpcen_kernel<<<4096, 512>>>(x, la, ld, lr, out);
}

// round 17
// speedup vs baseline: 1.0044x; 1.0039x over previous
#include <cuda_runtime.h>
#include <cuda_bf16.h>

// MRPCEN: multi-rate PCEN.
//   x: (32,128,2000) f32 ; log_alpha/log_delta/log_r: (128,) f32
//   out: (32,4,128,2000) f32, out[b,t,f,k]
// Per time-constant t: s = (sqrt(1+4t^2)-1)/(2t^2); IIR m[k]=(1-s)m[k-1]+s x[k], m[0]=x[0].
// smooth = (eps+M)^(-alpha); pcen = (x*smooth+delta)^r - delta^r.
//
// One block per (b,f) row. 512 threads = 4 groups x 128 threads (group = one t).
// x row staged in padded smem. Constant-coefficient parallel scan:
//   chunk length 16, carry factor A16=(1-s)^16, Kogge-Stone warp scan with
//   factor squaring, 3-step cross-warp combine. Exact algebra, all-positive
//   terms -> no cancellation.

#define TLEN 2000

__device__ __forceinline__ float ex2f_fast(float x) {
    float y; asm("ex2.approx.f32 %0, %1;" : "=f"(y) : "f"(x)); return y;
}
__device__ __forceinline__ float lg2f_fast(float x) {
    float y; asm("lg2.approx.f32 %0, %1;" : "=f"(y) : "f"(x)); return y;
}

__global__ void __launch_bounds__(512, 2)
mrpcen_kernel(const float* __restrict__ x,
              const float* __restrict__ log_alpha,
              const float* __restrict__ log_delta,
              const float* __restrict__ log_r,
              float* __restrict__ out)
{
    __shared__ float xs[2048 + 128];   // padded: index i stored at i + (i>>4)
    __shared__ float wsum[16];         // 4 groups x 4 warps

    const int bf = blockIdx.x;         // b*128 + f
    const int f  = bf & 127;
    const float* __restrict__ xrow = x + (long)bf * TLEN;

    const int tid = threadIdx.x;

    // ---- stage x row into smem (coalesced) ----
    #pragma unroll
    for (int i = 0; i < 4; ++i) {
        int idx = tid + i * 512;
        if (idx < TLEN) xs[idx + (idx >> 4)] = xrow[idx];
    }
    __syncthreads();

    const int g = tid >> 7;            // which time constant
    const int r = tid & 127;           // chunk index within row
    const int l = r & 31;              // lane in warp
    const int w = r >> 5;              // warp within group

    const float tconst = (g == 0) ? 4.f : (g == 1) ? 16.f : (g == 2) ? 64.f : 256.f;
    const float s = (sqrtf(fmaf(4.f * tconst, tconst, 1.f)) - 1.f) / (2.f * tconst * tconst);
    const float A = 1.f - s;
    const float A2 = A * A, A4 = A2 * A2, A8 = A4 * A4;
    const float A16 = A8 * A8;                                   // exact-ish via squaring
    const float log2A16 = 16.f * (log1pf(-s) * 1.4426950408889634f);

    const float x0 = xs[0];
    const int base = r * 16;           // first T index of this chunk
    const int sb   = 17 * r;           // padded smem base of this chunk

    // ---- pass 1: local chunk partial q (zero initial state) ----
    float q = 0.f;
    if (base < TLEN) {
        #pragma unroll
        for (int k = 0; k < 16; ++k)
            q = fmaf(A, q, s * xs[sb + k]);
    }

    // ---- warp-level Kogge-Stone scan of q with factor A16 ----
    float S  = q;
    float pw = A16;
    #pragma unroll
    for (int d = 1; d < 32; d <<= 1) {
        float up = __shfl_up_sync(0xffffffffu, S, d);
        if (l >= d) S = fmaf(pw, up, S);
        pw *= pw;                      // A16^(2d)
    }
    const float A16_32 = pw;           // A16^32

    if (l == 31) wsum[(g << 2) + w] = S;
    __syncthreads();

    // cross-warp incoming state H_w = scan value entering this warp
    float H = 0.f;
    #pragma unroll
    for (int v = 0; v < 3; ++v)
        if (v < w) H = fmaf(A16_32, H, wsum[(g << 2) + v]);

    // exclusive scan value for this chunk: E = A16^l * H + S_{l-1}
    float Sprev = __shfl_up_sync(0xffffffffu, S, 1);
    if (l == 0) Sprev = 0.f;
    const float E = fmaf(ex2f_fast(log2A16 * (float)l), H, Sprev);

    // state entering this chunk: m_start = A16^r * x0 + E   (m[-1] = x0)
    float m = fmaf(ex2f_fast(log2A16 * (float)r), x0, E);

    // ---- per-feature parameters ----
    const float alpha   = __expf(log_alpha[f]);
    const float delta   = __expf(log_delta[f]);
    const float rr      = __expf(log_r[f]);
    const float delta_r = ex2f_fast(rr * lg2f_fast(delta));
    const float nalpha  = -alpha;

    // ---- pass 2: recompute m with true state, PCEN math, float4 stores ----
    if (base < TLEN) {
        float* __restrict__ orow =
            out + ((((long)(bf >> 7)) * 4 + g) * 128 + f) * (long)TLEN + base;
        #pragma unroll
        for (int k4 = 0; k4 < 4; ++k4) {
            float4 v;
            float* vp = reinterpret_cast<float*>(&v);
            #pragma unroll
            for (int k = 0; k < 4; ++k) {
                const float xv = xs[sb + k4 * 4 + k];
                m = fmaf(A, m, s * xv);
                const float smooth = ex2f_fast(nalpha * lg2f_fast(m + 1e-5f));
                vp[k] = ex2f_fast(rr * lg2f_fast(fmaf(xv, smooth, delta))) - delta_r;
            }
            reinterpret_cast<float4*>(orow)[k4] = v;
        }
    }
}

extern "C" void kernel_launch(void* const* d_in, const int* in_sizes, int n_in,
                              void* d_out, int out_size)
{
    const float* x  = (const float*)d_in[0];
    const float* la = (const float*)d_in[1];
    const float* ld = (const float*)d_in[2];
    const float* lr = (const float*)d_in[3];
    float* out = (float*)d_out;

    // grid = B*F = 32*128 = 4096 blocks, 512 threads (4 t-groups x 128 chunks)
    mrpcen_kernel<<<4096, 512>>>(x, la, ld, lr, out);
}